// round 17
// baseline (speedup 1.0000x reference)
#include <cuda_runtime.h>
#include <cstdint>

// GatedDeltaRuleModule: 5-tap causal local attention. B=2, S=8192, H=16, D=128, W=4.
// out[b,s,h,:] = sum_{d=0..4} (q_s . k_{s-d}) * scale * sigmoid(a_s * b_{s-d}) * v_{s-d}
// out[b,0,h,:] = v[b,0,h,:]
//
// R16 = resubmission of R15 (Round 15 was a broker/container infra failure —
// the kernel never ran). R15 = R12 (persistent ticket grid, warp-strip
// streaming, per-warp cp.async ring PIPE=3, k/v history in rolling registers,
// tanh sigmoid, 25-SHFL butterfly) + de-risked transition machinery:
//  - next-ticket atomicAdd hoisted before halo loads (latency overlapped)
//  - next chunk's a/b gate strips prefetched into double-buffered smem via
//    cp.async during the current body
//  - SCALE folded into q once per row
// NOTE: redux.sync.add.f32 does NOT exist on sm_103 (R14 ptxas failure) —
// warp f32 reductions must be SHFL.

#define BATCH 2
#define SEQ   8192
#define HEADS 16
#define DIM   128
#define WIN   4
#define CH    32
#define THREADS 128
#define WPB   4
#define CHUNKS (SEQ / CH)                        // 256
#define TOTAL_CHUNKS (BATCH * HEADS * CHUNKS)    // 8192
#define NBLOCKS (148 * 8)                        // exactly 8 blocks/SM, one wave
#define NSLOT 4
#define PIPE  3
#define SLOT_FLOATS (3 * DIM)                    // q|k|v row = 1536 B

__device__ unsigned g_ticket;

__global__ void gdr_reset_ticket() { g_ticket = 0u; }

struct WarpSmem {
    float ring[NSLOT][SLOT_FLOATS];  // [0..127]=q, [128..255]=k, [256..383]=v
    float ash[2][CH];                // double-buffered gate strips
    float bsh[2][CH + WIN];          // bsh[buf][j] = b[s0-4+j]
};

__device__ __forceinline__ float dot4(const float4 a, const float4 b) {
    return a.x * b.x + a.y * b.y + a.z * b.z + a.w * b.w;
}

__device__ __forceinline__ void cp16(uint32_t saddr, const float* g) {
    asm volatile("cp.async.cg.shared.global [%0], [%1], 16;" :: "r"(saddr), "l"(g));
}

__device__ __forceinline__ void cp4(float* smem_dst, const float* g) {
    uint32_t s = (uint32_t)__cvta_generic_to_shared(smem_dst);
    asm volatile("cp.async.ca.shared.global [%0], [%1], 4;" :: "r"(s), "l"(g));
}

// sigmoid(x) = 0.5*tanh(0.5x) + 0.5  (single MUFU.TANH, ~1e-4 abs err)
__device__ __forceinline__ float sigmoid_tanh(float x) {
    float t;
    asm("tanh.approx.f32 %0, %1;" : "=f"(t) : "f"(0.5f * x));
    return fmaf(0.5f, t, 0.5f);
}

__global__ __launch_bounds__(THREADS, 8)
void gdr_persist_kernel(const float* __restrict__ q,
                        const float* __restrict__ k,
                        const float* __restrict__ v,
                        const float* __restrict__ a,
                        const float* __restrict__ b,
                        float* __restrict__ out)
{
    __shared__ WarpSmem wsm[WPB];

    const int lane = threadIdx.x & 31;
    const int wid  = threadIdx.x >> 5;
    WarpSmem& S = wsm[wid];

    const float  SCALE     = 0.08838834764831845f;  // 1/sqrt(128)
    const size_t ROWSTRIDE = (size_t)HEADS * DIM;   // 2048 floats
    const uint32_t ring0 =
        (uint32_t)__cvta_generic_to_shared(&S.ring[0][0]) + (uint32_t)(lane * 16);

    // ---- First ticket + direct a/b load into buffer 0 ----
    unsigned t;
    if (lane == 0) t = atomicAdd(&g_ticket, 1u);
    t = __shfl_sync(0xffffffffu, t, 0);

    if (t < TOTAL_CHUNKS) {
        const int c0 = t & (CHUNKS - 1);
        const int h0 = (t >> 8) & (HEADS - 1);
        const int b0 = (int)(t >> 12);
        const int s00 = c0 * CH;
        for (int j = lane; j < CH + WIN; j += 32) {
            const int s = s00 - WIN + j;
            S.bsh[0][j] = (s >= 0) ? b[((size_t)b0 * SEQ + s) * HEADS + h0] : 0.f;
        }
        S.ash[0][lane] = a[((size_t)b0 * SEQ + s00 + lane) * HEADS + h0];  // CH==32
    }
    __syncwarp();

    int buf = 0;

    while (t < TOTAL_CHUNKS) {
        const int chunk = t & (CHUNKS - 1);          // bits 0..7
        const int h     = (t >> 8) & (HEADS - 1);    // bits 8..11
        const int bb    = (int)(t >> 12);            // bit 12
        const int s0    = chunk * CH;

        // Issue next-ticket atomic FIRST: its ~318-cyc latency overlaps the
        // halo LDGs + prologue cp.asyncs issued below.
        unsigned tn = 0xffffffffu;
        if (lane == 0) tn = atomicAdd(&g_ticket, 1u);

        const size_t off0 = (((size_t)bb * SEQ + s0) * HEADS + h) * DIM;
        const float* qp = q + off0 + lane * 4;
        const float* kp = k + off0 + lane * 4;
        const float* vp = v + off0 + lane * 4;
        float*       op = out + off0 + lane * 4;

        // ---- k/v halo window (rows s0-1..s0-4); zero for s0==0 (padding) ----
        const float4 z4 = make_float4(0.f, 0.f, 0.f, 0.f);
        float4 k1 = z4, k2 = z4, k3 = z4, k4 = z4;
        float4 v1 = z4, v2 = z4, v3 = z4, v4 = z4;
        if (s0 != 0) {  // s0 multiple of CH=32 => all 4 halo rows exist
            k1 = *reinterpret_cast<const float4*>(kp - 1 * ROWSTRIDE);
            v1 = *reinterpret_cast<const float4*>(vp - 1 * ROWSTRIDE);
            k2 = *reinterpret_cast<const float4*>(kp - 2 * ROWSTRIDE);
            v2 = *reinterpret_cast<const float4*>(vp - 2 * ROWSTRIDE);
            k3 = *reinterpret_cast<const float4*>(kp - 3 * ROWSTRIDE);
            v3 = *reinterpret_cast<const float4*>(vp - 3 * ROWSTRIDE);
            k4 = *reinterpret_cast<const float4*>(kp - 4 * ROWSTRIDE);
            v4 = *reinterpret_cast<const float4*>(vp - 4 * ROWSTRIDE);
        }

        // ---- Pipeline prologue: stage rows 0..PIPE-1 ----
#pragma unroll
        for (int i = 0; i < PIPE; i++) {
            const uint32_t dst = ring0 + (uint32_t)((i & (NSLOT - 1)) * SLOT_FLOATS * 4);
            cp16(dst,               qp + (size_t)i * ROWSTRIDE);
            cp16(dst + DIM * 4,     kp + (size_t)i * ROWSTRIDE);
            cp16(dst + 2 * DIM * 4, vp + (size_t)i * ROWSTRIDE);
            asm volatile("cp.async.commit_group;" ::: "memory");
        }

        // ---- Resolve next ticket; prefetch its a/b strips into buf^1 ----
        tn = __shfl_sync(0xffffffffu, tn, 0);
        const int nb = buf ^ 1;
        if (tn < TOTAL_CHUNKS) {
            const int cn  = tn & (CHUNKS - 1);
            const int hn  = (tn >> 8) & (HEADS - 1);
            const int bbn = (int)(tn >> 12);
            const int s0n = cn * CH;
            // ash: always valid (CH==32, one element per lane)
            cp4(&S.ash[nb][lane], a + ((size_t)bbn * SEQ + s0n + lane) * HEADS + hn);
            // bsh main: lanes 0..3 map to s<0 only when s0n==0 -> plain STS zero
            const int sb = s0n - WIN + lane;
            if (sb >= 0)
                cp4(&S.bsh[nb][lane], b + ((size_t)bbn * SEQ + sb) * HEADS + hn);
            else
                S.bsh[nb][lane] = 0.f;
            // bsh extras j=32..35 (always valid: s = s0n+28..s0n+31)
            if (lane < WIN)
                cp4(&S.bsh[nb][CH + lane],
                    b + ((size_t)bbn * SEQ + s0n + (CH - WIN) + lane) * HEADS + hn);
            // These cp.asyncs join body iter-0's commit group; complete by
            // iter-31's wait_group 2, visible after the transition __syncwarp —
            // a full chunk before first use.
        }

        const bool first_chunk = (s0 == 0);

#pragma unroll 4
        for (int i = 0; i < CH; ++i) {
            // Completed groups >= i+1 -> row i's data has landed.
            asm volatile("cp.async.wait_group 2;" ::: "memory");

            const int slot = i & (NSLOT - 1);
            // Each lane reads exactly the 16B it staged itself: no syncwarp.
            float4 cq = *reinterpret_cast<const float4*>(&S.ring[slot][lane * 4]);
            const float4 ck = *reinterpret_cast<const float4*>(&S.ring[slot][DIM + lane * 4]);
            const float4 cv = *reinterpret_cast<const float4*>(&S.ring[slot][2 * DIM + lane * 4]);
            // Fold the attention scale into q once (saves a mul per tap).
            cq.x *= SCALE; cq.y *= SCALE; cq.z *= SCALE; cq.w *= SCALE;

            // Stage row i+PIPE into slot (i-1)&3 — consumed last iteration.
            if (i + PIPE < CH) {
                const uint32_t dst =
                    ring0 + (uint32_t)(((i + PIPE) & (NSLOT - 1)) * SLOT_FLOATS * 4);
                cp16(dst,               qp + (size_t)(i + PIPE) * ROWSTRIDE);
                cp16(dst + DIM * 4,     kp + (size_t)(i + PIPE) * ROWSTRIDE);
                cp16(dst + 2 * DIM * 4, vp + (size_t)(i + PIPE) * ROWSTRIDE);
            }
            asm volatile("cp.async.commit_group;" ::: "memory");  // uniform group count

            // 5 per-lane dot partials
            float p0 = dot4(cq, ck);
            float p1 = dot4(cq, k1);
            float p2 = dot4(cq, k2);
            float p3 = dot4(cq, k3);
            float p4 = dot4(cq, k4);

            // Full-warp butterfly, 5 taps interleaved (25 SHFL).
            // (redux.sync.add.f32 does not exist on sm_103 — SHFL is the only path.)
#pragma unroll
            for (int offx = 16; offx > 0; offx >>= 1) {
                p0 += __shfl_xor_sync(0xffffffffu, p0, offx);
                p1 += __shfl_xor_sync(0xffffffffu, p1, offx);
                p2 += __shfl_xor_sync(0xffffffffu, p2, offx);
                p3 += __shfl_xor_sync(0xffffffffu, p3, offx);
                p4 += __shfl_xor_sync(0xffffffffu, p4, offx);
            }

            // Gates from smem (LDS broadcast). bsh[buf][i+4-d] = b[s-d]; halo
            // rows zero-filled -> p==0 there, matching reference zero-padding.
            const float ca = S.ash[buf][i];
            const float c0 = p0 * sigmoid_tanh(ca * S.bsh[buf][i + 4]);
            const float c1 = p1 * sigmoid_tanh(ca * S.bsh[buf][i + 3]);
            const float c2 = p2 * sigmoid_tanh(ca * S.bsh[buf][i + 2]);
            const float c3 = p3 * sigmoid_tanh(ca * S.bsh[buf][i + 1]);
            const float c4 = p4 * sigmoid_tanh(ca * S.bsh[buf][i + 0]);

            float4 acc;
            acc.x = c0 * cv.x + c1 * v1.x + c2 * v2.x + c3 * v3.x + c4 * v4.x;
            acc.y = c0 * cv.y + c1 * v1.y + c2 * v2.y + c3 * v3.y + c4 * v4.y;
            acc.z = c0 * cv.z + c1 * v1.z + c2 * v2.z + c3 * v3.z + c4 * v4.z;
            acc.w = c0 * cv.w + c1 * v1.w + c2 * v2.w + c3 * v3.w + c4 * v4.w;

            if (first_chunk && i == 0)  // reference special-cases s==0: out = v_0
                acc = cv;

            // Streaming store: out is never re-read.
            __stcs(reinterpret_cast<float4*>(op + (size_t)i * ROWSTRIDE), acc);

            // Slide history window (renamed under unroll-4)
            k4 = k3; k3 = k2; k2 = k1; k1 = ck;
            v4 = v3; v3 = v2; v2 = v1; v1 = cv;
        }

        t = tn;
        buf ^= 1;
        // Makes the prefetched a/b strips in the new buf visible across lanes;
        // their completion was covered by iter-31's wait_group 2.
        __syncwarp();
    }
}

extern "C" void kernel_launch(void* const* d_in, const int* in_sizes, int n_in,
                              void* d_out, int out_size)
{
    const float* q = (const float*)d_in[0];
    const float* k = (const float*)d_in[1];
    const float* v = (const float*)d_in[2];
    const float* a = (const float*)d_in[3];
    const float* b = (const float*)d_in[4];
    float* out = (float*)d_out;

    gdr_reset_ticket<<<1, 1>>>();
    gdr_persist_kernel<<<NBLOCKS, THREADS>>>(q, k, v, a, b, out);
}